// round 2
// baseline (speedup 1.0000x reference)
#include <cuda_runtime.h>
#include <cstdint>

// Problem constants
#define Bn  4
#define Sn  2048
#define Dn  1024
#define NHh 16
#define HDd 64
#define MTOT (Bn * Sn)   // 8192

// Scratch (static __device__ — no allocations allowed)
__device__ float g_Qt[Bn * NHh * HDd * Sn];   // [bh][hd][s]  (transposed heads, pre-scaled)
__device__ float g_Kt[Bn * NHh * HDd * Sn];   // [bh][hd][s]
__device__ float g_V [Bn * NHh * Sn * HDd];   // [bh][s][hd]
__device__ float g_Y [Bn * Sn * Dn];          // [b][s][d] attention output

// ---------------------------------------------------------------------------
// GEMM: C = A @ W^T.  A: [M, 1024] row-major, W: [1024, 1024] row-major (n,k).
// mode 0: write head-TRANSPOSED: C[((b*NH+h)*HD+hd)*S + s] = acc*scale
// mode 1: write head-natural:    C[((b*NH+h)*S+s)*HD + hd] = acc*scale
// mode 2: plain row-major:       C[m*1024 + n]             = acc*scale
// ---------------------------------------------------------------------------
__global__ __launch_bounds__(256, 2)
void gemm_nt(const float* __restrict__ A, const float* __restrict__ W,
             float* __restrict__ C, int mode, float scale)
{
    constexpr int BM = 128, BN = 128, BK = 16;
    __shared__ float As[2][BK][BM];
    __shared__ float Bs[2][BK][BN];

    const int tid = threadIdx.x;
    const int tx  = tid & 15;
    const int ty  = tid >> 4;
    const int m0  = blockIdx.x * BM;
    const int n0  = blockIdx.y * BN;

    // tile loader mapping: each thread loads one half-row (8 floats) of A and W
    const int lr = tid >> 1;            // row within tile 0..127
    const int lc = (tid & 1) * 8;       // starting k-col: 0 or 8
    const float* Ap = A + (size_t)(m0 + lr) * Dn + lc;
    const float* Wp = W + (size_t)(n0 + lr) * Dn + lc;

    float4 pa0, pa1, pb0, pb1;

    float acc[8][8];
#pragma unroll
    for (int i = 0; i < 8; ++i)
#pragma unroll
        for (int j = 0; j < 8; ++j) acc[i][j] = 0.0f;

    // prefetch tile 0
    {
        const float* a = Ap;
        pa0 = *reinterpret_cast<const float4*>(a);
        pa1 = *reinterpret_cast<const float4*>(a + 4);
        const float* w = Wp;
        pb0 = *reinterpret_cast<const float4*>(w);
        pb1 = *reinterpret_cast<const float4*>(w + 4);
        As[0][lc + 0][lr] = pa0.x; As[0][lc + 1][lr] = pa0.y;
        As[0][lc + 2][lr] = pa0.z; As[0][lc + 3][lr] = pa0.w;
        As[0][lc + 4][lr] = pa1.x; As[0][lc + 5][lr] = pa1.y;
        As[0][lc + 6][lr] = pa1.z; As[0][lc + 7][lr] = pa1.w;
        Bs[0][lc + 0][lr] = pb0.x; Bs[0][lc + 1][lr] = pb0.y;
        Bs[0][lc + 2][lr] = pb0.z; Bs[0][lc + 3][lr] = pb0.w;
        Bs[0][lc + 4][lr] = pb1.x; Bs[0][lc + 5][lr] = pb1.y;
        Bs[0][lc + 6][lr] = pb1.z; Bs[0][lc + 7][lr] = pb1.w;
    }
    __syncthreads();

    constexpr int NT = Dn / BK;  // 64
    for (int kt = 0; kt < NT; ++kt) {
        const int cur = kt & 1;
        if (kt + 1 < NT) {
            const float* a = Ap + (kt + 1) * BK;
            pa0 = *reinterpret_cast<const float4*>(a);
            pa1 = *reinterpret_cast<const float4*>(a + 4);
            const float* w = Wp + (kt + 1) * BK;
            pb0 = *reinterpret_cast<const float4*>(w);
            pb1 = *reinterpret_cast<const float4*>(w + 4);
        }
#pragma unroll
        for (int kk = 0; kk < BK; ++kk) {
            float av[8], bv[8];
            *reinterpret_cast<float4*>(&av[0]) = *reinterpret_cast<const float4*>(&As[cur][kk][ty * 8]);
            *reinterpret_cast<float4*>(&av[4]) = *reinterpret_cast<const float4*>(&As[cur][kk][ty * 8 + 4]);
            *reinterpret_cast<float4*>(&bv[0]) = *reinterpret_cast<const float4*>(&Bs[cur][kk][tx * 8]);
            *reinterpret_cast<float4*>(&bv[4]) = *reinterpret_cast<const float4*>(&Bs[cur][kk][tx * 8 + 4]);
#pragma unroll
            for (int i = 0; i < 8; ++i)
#pragma unroll
                for (int j = 0; j < 8; ++j)
                    acc[i][j] += av[i] * bv[j];
        }
        if (kt + 1 < NT) {
            const int nxt = (kt + 1) & 1;
            As[nxt][lc + 0][lr] = pa0.x; As[nxt][lc + 1][lr] = pa0.y;
            As[nxt][lc + 2][lr] = pa0.z; As[nxt][lc + 3][lr] = pa0.w;
            As[nxt][lc + 4][lr] = pa1.x; As[nxt][lc + 5][lr] = pa1.y;
            As[nxt][lc + 6][lr] = pa1.z; As[nxt][lc + 7][lr] = pa1.w;
            Bs[nxt][lc + 0][lr] = pb0.x; Bs[nxt][lc + 1][lr] = pb0.y;
            Bs[nxt][lc + 2][lr] = pb0.z; Bs[nxt][lc + 3][lr] = pb0.w;
            Bs[nxt][lc + 4][lr] = pb1.x; Bs[nxt][lc + 5][lr] = pb1.y;
            Bs[nxt][lc + 6][lr] = pb1.z; Bs[nxt][lc + 7][lr] = pb1.w;
        }
        __syncthreads();
    }

    // Epilogue
    if (mode == 2) {
#pragma unroll
        for (int i = 0; i < 8; ++i) {
            float* dst = C + (size_t)(m0 + ty * 8 + i) * Dn + n0 + tx * 8;
            float4 v0 = make_float4(acc[i][0] * scale, acc[i][1] * scale,
                                    acc[i][2] * scale, acc[i][3] * scale);
            float4 v1 = make_float4(acc[i][4] * scale, acc[i][5] * scale,
                                    acc[i][6] * scale, acc[i][7] * scale);
            *reinterpret_cast<float4*>(dst)     = v0;
            *reinterpret_cast<float4*>(dst + 4) = v1;
        }
    } else if (mode == 1) {
#pragma unroll
        for (int i = 0; i < 8; ++i) {
            const int m = m0 + ty * 8 + i;
            const int b = m >> 11;
            const int s = m & (Sn - 1);
            const int n = n0 + tx * 8;
            const int h  = n >> 6;
            const int hd = n & 63;
            float* dst = C + ((size_t)((b * NHh + h) * Sn + s)) * HDd + hd;
            float4 v0 = make_float4(acc[i][0] * scale, acc[i][1] * scale,
                                    acc[i][2] * scale, acc[i][3] * scale);
            float4 v1 = make_float4(acc[i][4] * scale, acc[i][5] * scale,
                                    acc[i][6] * scale, acc[i][7] * scale);
            *reinterpret_cast<float4*>(dst)     = v0;
            *reinterpret_cast<float4*>(dst + 4) = v1;
        }
    } else {
#pragma unroll
        for (int i = 0; i < 8; ++i) {
            const int m = m0 + ty * 8 + i;
            const int b = m >> 11;
            const int s = m & (Sn - 1);
#pragma unroll
            for (int j = 0; j < 8; ++j) {
                const int n  = n0 + tx * 8 + j;
                const int h  = n >> 6;
                const int hd = n & 63;
                C[((size_t)((b * NHh + h) * HDd + hd)) * Sn + s] = acc[i][j] * scale;
            }
        }
    }
}

// ---------------------------------------------------------------------------
// Flash attention: per (b, h, q-tile of 128). Tk = 64.
// Qt/Kt: [bh][hd][s] (Q pre-scaled by 1/sqrt(HD)); V: [bh][s][hd].
// Output Y: [b][s][h*64+hd]  (natural [B,S,D]).
// ---------------------------------------------------------------------------
#define TQ 128
#define TK 64
#define PSTR 132   // padded stride for P^T tile

__global__ __launch_bounds__(256, 2)
void attn_kernel(const float* __restrict__ Qt, const float* __restrict__ Kt,
                 const float* __restrict__ V, float* __restrict__ Y)
{
    extern __shared__ float sm[];
    float* Qs = sm;                     // [64][128]  Qs[hd*128 + q]
    float* Ks = Qs + HDd * TQ;          // [64][64]   Ks[hd*64 + k]
    float* Vs = Ks + HDd * TK;          // [64][64]   Vs[k*64 + hd]
    float* Ps = Vs + TK * HDd;          // [64][132]  Ps[k*132 + q]  (P transposed)

    const int tid = threadIdx.x;
    const int tx  = tid & 15;
    const int ty  = tid >> 4;
    const int q0  = blockIdx.x * TQ;
    const int h   = blockIdx.y;
    const int b   = blockIdx.z;
    const int bh  = b * NHh + h;

    // Load Q tile [hd][q]: coalesced copy, no transpose needed
    {
        const float* Qb = Qt + (size_t)bh * HDd * Sn + q0;
        for (int f = tid; f < HDd * TQ / 4; f += 256) {
            const int row = f >> 5;       // 32 float4 per 128-float row
            const int c4  = f & 31;
            *reinterpret_cast<float4*>(Qs + row * TQ + c4 * 4) =
                *reinterpret_cast<const float4*>(Qb + (size_t)row * Sn + c4 * 4);
        }
    }

    float m_[8], l_[8], o_[8][4];
#pragma unroll
    for (int i = 0; i < 8; ++i) {
        m_[i] = -1e30f;
        l_[i] = 0.0f;
#pragma unroll
        for (int j = 0; j < 4; ++j) o_[i][j] = 0.0f;
    }

    const float* Kb = Kt + (size_t)bh * HDd * Sn;
    const float* Vb = V  + (size_t)bh * Sn * HDd;

    for (int k0 = 0; k0 < Sn; k0 += TK) {
        __syncthreads();   // prior-iter Ps/Vs/Ks consumers done (and Qs visible, iter 0)

        // Load K tile [hd][k] and V tile [k][hd]
        for (int f = tid; f < HDd * TK / 4; f += 256) {
            const int row = f >> 4;       // 16 float4 per 64-float row
            const int c4  = f & 15;
            *reinterpret_cast<float4*>(Ks + row * TK + c4 * 4) =
                *reinterpret_cast<const float4*>(Kb + (size_t)row * Sn + k0 + c4 * 4);
        }
        for (int f = tid; f < TK * HDd / 4; f += 256) {
            const int row = f >> 4;
            const int c4  = f & 15;
            *reinterpret_cast<float4*>(Vs + row * HDd + c4 * 4) =
                *reinterpret_cast<const float4*>(Vb + (size_t)(k0 + row) * HDd + c4 * 4);
        }
        __syncthreads();

        // S[i][j] = sum_hd Qs[hd][ty*8+i] * Ks[hd][tx*4+j]   (Q already scaled)
        float s[8][4];
#pragma unroll
        for (int i = 0; i < 8; ++i)
#pragma unroll
            for (int j = 0; j < 4; ++j) s[i][j] = 0.0f;

#pragma unroll
        for (int kk = 0; kk < HDd; ++kk) {
            float av[8], bv[4];
            *reinterpret_cast<float4*>(&av[0]) = *reinterpret_cast<const float4*>(Qs + kk * TQ + ty * 8);
            *reinterpret_cast<float4*>(&av[4]) = *reinterpret_cast<const float4*>(Qs + kk * TQ + ty * 8 + 4);
            *reinterpret_cast<float4*>(&bv[0]) = *reinterpret_cast<const float4*>(Ks + kk * TK + tx * 4);
#pragma unroll
            for (int i = 0; i < 8; ++i)
#pragma unroll
                for (int j = 0; j < 4; ++j)
                    s[i][j] += av[i] * bv[j];
        }

        // Online softmax (row reductions across the 16 tx lanes of each 16-lane group)
#pragma unroll
        for (int i = 0; i < 8; ++i) {
            float rmax = fmaxf(fmaxf(s[i][0], s[i][1]), fmaxf(s[i][2], s[i][3]));
#pragma unroll
            for (int off = 1; off < 16; off <<= 1)
                rmax = fmaxf(rmax, __shfl_xor_sync(0xffffffffu, rmax, off, 16));
            const float mnew  = fmaxf(m_[i], rmax);
            const float alpha = __expf(m_[i] - mnew);
            float rsum = 0.0f;
#pragma unroll
            for (int j = 0; j < 4; ++j) {
                const float p = __expf(s[i][j] - mnew);
                s[i][j] = p;           // reuse s as P storage
                rsum += p;
            }
#pragma unroll
            for (int off = 1; off < 16; off <<= 1)
                rsum += __shfl_xor_sync(0xffffffffu, rsum, off, 16);
            l_[i] = l_[i] * alpha + rsum;
            m_[i] = mnew;
#pragma unroll
            for (int j = 0; j < 4; ++j) o_[i][j] *= alpha;
        }

        // Store P transposed: Ps[k = tx*4+j][q = ty*8 + i]
#pragma unroll
        for (int j = 0; j < 4; ++j) {
            float4 v0 = make_float4(s[0][j], s[1][j], s[2][j], s[3][j]);
            float4 v1 = make_float4(s[4][j], s[5][j], s[6][j], s[7][j]);
            float* dst = Ps + (tx * 4 + j) * PSTR + ty * 8;
            *reinterpret_cast<float4*>(dst)     = v0;
            *reinterpret_cast<float4*>(dst + 4) = v1;
        }
        __syncthreads();

        // O[i][j] += sum_k P[q][k] * V[k][hd] ;  P[q][k] = Ps[k][q]
#pragma unroll
        for (int kk = 0; kk < TK; ++kk) {
            float av[8], bv[4];
            *reinterpret_cast<float4*>(&av[0]) = *reinterpret_cast<const float4*>(Ps + kk * PSTR + ty * 8);
            *reinterpret_cast<float4*>(&av[4]) = *reinterpret_cast<const float4*>(Ps + kk * PSTR + ty * 8 + 4);
            *reinterpret_cast<float4*>(&bv[0]) = *reinterpret_cast<const float4*>(Vs + kk * HDd + tx * 4);
#pragma unroll
            for (int i = 0; i < 8; ++i)
#pragma unroll
                for (int j = 0; j < 4; ++j)
                    o_[i][j] += av[i] * bv[j];
        }
    }

    // Epilogue: normalize, write Y in [B,S,D] layout
#pragma unroll
    for (int i = 0; i < 8; ++i) {
        const float inv = 1.0f / l_[i];
        const int q = q0 + ty * 8 + i;
        float4 v = make_float4(o_[i][0] * inv, o_[i][1] * inv,
                               o_[i][2] * inv, o_[i][3] * inv);
        *reinterpret_cast<float4*>(Y + ((size_t)(b * Sn + q)) * Dn + h * HDd + tx * 4) = v;
    }
}

// ---------------------------------------------------------------------------
extern "C" void kernel_launch(void* const* d_in, const int* in_sizes, int n_in,
                              void* d_out, int out_size)
{
    const float* x  = (const float*)d_in[0];
    const float* Wq = (const float*)d_in[1];
    const float* Wk = (const float*)d_in[2];
    const float* Wv = (const float*)d_in[3];
    const float* Wo = (const float*)d_in[4];
    float* out = (float*)d_out;

    float *qt, *kt, *v, *y;
    cudaGetSymbolAddress((void**)&qt, g_Qt);
    cudaGetSymbolAddress((void**)&kt, g_Kt);
    cudaGetSymbolAddress((void**)&v,  g_V);
    cudaGetSymbolAddress((void**)&y,  g_Y);

    constexpr int ATTN_SMEM = (HDd * TQ + HDd * TK + TK * HDd + TK * PSTR) * (int)sizeof(float); // 99328
    cudaFuncSetAttribute(attn_kernel, cudaFuncAttributeMaxDynamicSharedMemorySize, ATTN_SMEM);

    const dim3 gg(MTOT / 128, Dn / 128);

    // Projections (scale 1/sqrt(64) folded into Q)
    gemm_nt<<<gg, 256>>>(x, Wq, qt, 0, 0.125f);
    gemm_nt<<<gg, 256>>>(x, Wk, kt, 0, 1.0f);
    gemm_nt<<<gg, 256>>>(x, Wv, v,  1, 1.0f);

    // Flash attention
    attn_kernel<<<dim3(Sn / TQ, NHh, Bn), 256, ATTN_SMEM>>>(qt, kt, v, y);

    // Output projection
    gemm_nt<<<gg, 256>>>(y, Wo, out, 2, 1.0f);
}

// round 4
// speedup vs baseline: 1.3621x; 1.3621x over previous
#include <cuda_runtime.h>
#include <cstdint>

// Problem constants
#define Bn  4
#define Sn  2048
#define Dn  1024
#define NHh 16
#define HDd 64
#define MTOT (Bn * Sn)   // 8192

// Scratch (static __device__ — no allocations allowed)
__device__ float g_Qt[Bn * NHh * HDd * Sn];   // [bh][hd][s]  (transposed heads, pre-scaled)
__device__ float g_Kt[Bn * NHh * HDd * Sn];   // [bh][hd][s]
__device__ float g_V [Bn * NHh * Sn * HDd];   // [bh][s][hd]
__device__ float g_Y [Bn * Sn * Dn];          // [b][s][d] attention output

// ---------------------------------------------------------------------------
// tf32 helpers (base PTX ISA — works on compute_100 virtual arch)
// ---------------------------------------------------------------------------
__device__ __forceinline__ uint32_t f2tf32(float f) {
    uint32_t r;
    asm("cvt.rna.tf32.f32 %0, %1;" : "=r"(r) : "f"(f));
    return r;
}

__device__ __forceinline__ void mma_tf32(float c[4],
                                         uint32_t a0, uint32_t a1, uint32_t a2, uint32_t a3,
                                         uint32_t b0, uint32_t b1) {
    asm volatile(
        "mma.sync.aligned.m16n8k8.row.col.f32.tf32.tf32.f32 "
        "{%0,%1,%2,%3}, {%4,%5,%6,%7}, {%8,%9}, {%0,%1,%2,%3};"
        : "+f"(c[0]), "+f"(c[1]), "+f"(c[2]), "+f"(c[3])
        : "r"(a0), "r"(a1), "r"(a2), "r"(a3), "r"(b0), "r"(b1));
}

// ===========================================================================
// Tensor-core GEMM: C = A @ W^T (tf32 mma.sync).
// A: [M, 1024] fp32 K-major, W: [1024, 1024] fp32 K-major (n,k rows).
// CTA tile 128x128, BK=16, double-buffered smem, warp grid 2(M) x 4(N),
// warp tile 64x32 via m16n8k8 fragments (4 A-frags x 4 B-frags).
// mode 0: head-transposed:  C[((b*NH+h)*HD+hd)*S + s]
// mode 1: head-natural:     C[((b*NH+h)*S+s)*HD + hd]
// mode 2: plain row-major:  C[m*1024 + n]
// ===========================================================================
#define GSTR 20   // smem row stride (floats): conflict-free fragment loads, 16B-aligned rows

__global__ __launch_bounds__(256, 1)
void gemm_mma(const float* __restrict__ A, const float* __restrict__ W,
              float* __restrict__ C, int mode, float scale)
{
    constexpr int BM = 128, BK = 16;
    __shared__ uint32_t As[2][BM * GSTR];
    __shared__ uint32_t Bs[2][BM * GSTR];

    const int tid  = threadIdx.x;
    const int wid  = tid >> 5;
    const int lane = tid & 31;
    const int wm   = wid >> 2;        // 0..1
    const int wn   = wid & 3;         // 0..3
    const int mw   = wm * 64;
    const int nw   = wn * 32;
    const int g    = lane >> 2;       // 0..7
    const int t    = lane & 3;        // 0..3
    const int m0   = blockIdx.x * 128;
    const int n0   = blockIdx.y * 128;

    // Loader mapping: each thread loads one 16-float half-row split as 2 float4
    const int lr = tid >> 1;            // row 0..127 (A row and W row)
    const int lc = (tid & 1) * 8;       // k-col 0 or 8
    const float* Ap = A + (size_t)(m0 + lr) * Dn + lc;
    const float* Wp = W + (size_t)(n0 + lr) * Dn + lc;

    float4 pa0, pa1, pb0, pb1;

    float c[4][4][4];
#pragma unroll
    for (int i = 0; i < 4; ++i)
#pragma unroll
        for (int j = 0; j < 4; ++j)
#pragma unroll
            for (int e = 0; e < 4; ++e) c[i][j][e] = 0.0f;

    // prefetch tile 0 into regs, store converted
    {
        pa0 = *reinterpret_cast<const float4*>(Ap);
        pa1 = *reinterpret_cast<const float4*>(Ap + 4);
        pb0 = *reinterpret_cast<const float4*>(Wp);
        pb1 = *reinterpret_cast<const float4*>(Wp + 4);
        uint32_t* da = &As[0][lr * GSTR + lc];
        da[0] = f2tf32(pa0.x); da[1] = f2tf32(pa0.y);
        da[2] = f2tf32(pa0.z); da[3] = f2tf32(pa0.w);
        da[4] = f2tf32(pa1.x); da[5] = f2tf32(pa1.y);
        da[6] = f2tf32(pa1.z); da[7] = f2tf32(pa1.w);
        uint32_t* db = &Bs[0][lr * GSTR + lc];
        db[0] = f2tf32(pb0.x); db[1] = f2tf32(pb0.y);
        db[2] = f2tf32(pb0.z); db[3] = f2tf32(pb0.w);
        db[4] = f2tf32(pb1.x); db[5] = f2tf32(pb1.y);
        db[6] = f2tf32(pb1.z); db[7] = f2tf32(pb1.w);
    }
    __syncthreads();

    constexpr int NT = Dn / BK;   // 64 k-tiles
    for (int kt = 0; kt < NT; ++kt) {
        const int cur = kt & 1;
        if (kt + 1 < NT) {
            const float* a = Ap + (kt + 1) * BK;
            pa0 = *reinterpret_cast<const float4*>(a);
            pa1 = *reinterpret_cast<const float4*>(a + 4);
            const float* w = Wp + (kt + 1) * BK;
            pb0 = *reinterpret_cast<const float4*>(w);
            pb1 = *reinterpret_cast<const float4*>(w + 4);
        }

#pragma unroll
        for (int ks = 0; ks < BK; ks += 8) {
            uint32_t a[4][4], b[4][2];
#pragma unroll
            for (int f = 0; f < 4; ++f) {
                const int r = mw + f * 16 + g;
                a[f][0] = As[cur][r * GSTR + ks + t];
                a[f][1] = As[cur][(r + 8) * GSTR + ks + t];
                a[f][2] = As[cur][r * GSTR + ks + t + 4];
                a[f][3] = As[cur][(r + 8) * GSTR + ks + t + 4];
            }
#pragma unroll
            for (int f = 0; f < 4; ++f) {
                const int n = nw + f * 8 + g;
                b[f][0] = Bs[cur][n * GSTR + ks + t];
                b[f][1] = Bs[cur][n * GSTR + ks + t + 4];
            }
#pragma unroll
            for (int i = 0; i < 4; ++i)
#pragma unroll
                for (int j = 0; j < 4; ++j)
                    mma_tf32(c[i][j], a[i][0], a[i][1], a[i][2], a[i][3],
                             b[j][0], b[j][1]);
        }

        if (kt + 1 < NT) {
            const int nxt = (kt + 1) & 1;
            uint32_t* da = &As[nxt][lr * GSTR + lc];
            da[0] = f2tf32(pa0.x); da[1] = f2tf32(pa0.y);
            da[2] = f2tf32(pa0.z); da[3] = f2tf32(pa0.w);
            da[4] = f2tf32(pa1.x); da[5] = f2tf32(pa1.y);
            da[6] = f2tf32(pa1.z); da[7] = f2tf32(pa1.w);
            uint32_t* db = &Bs[nxt][lr * GSTR + lc];
            db[0] = f2tf32(pb0.x); db[1] = f2tf32(pb0.y);
            db[2] = f2tf32(pb0.z); db[3] = f2tf32(pb0.w);
            db[4] = f2tf32(pb1.x); db[5] = f2tf32(pb1.y);
            db[6] = f2tf32(pb1.z); db[7] = f2tf32(pb1.w);
        }
        __syncthreads();
    }

    // Epilogue: fragment (i,j): rows r0 = m0+mw+i*16+g, r1 = r0+8;
    //           cols col0 = n0+nw+j*8+2t, col1 = col0+1.
#pragma unroll
    for (int i = 0; i < 4; ++i) {
        const int r0 = m0 + mw + i * 16 + g;
        const int r1 = r0 + 8;
#pragma unroll
        for (int j = 0; j < 4; ++j) {
            const int col0 = n0 + nw + j * 8 + 2 * t;
            const float v00 = c[i][j][0] * scale;   // (r0, col0)
            const float v01 = c[i][j][1] * scale;   // (r0, col0+1)
            const float v10 = c[i][j][2] * scale;   // (r1, col0)
            const float v11 = c[i][j][3] * scale;   // (r1, col0+1)
            if (mode == 2) {
                *reinterpret_cast<float2*>(C + (size_t)r0 * Dn + col0) = make_float2(v00, v01);
                *reinterpret_cast<float2*>(C + (size_t)r1 * Dn + col0) = make_float2(v10, v11);
            } else if (mode == 1) {
                const int h   = col0 >> 6;
                const int hd  = col0 & 63;
                const int b0i = r0 >> 11, s0 = r0 & (Sn - 1);
                const int b1i = r1 >> 11, s1 = r1 & (Sn - 1);
                *reinterpret_cast<float2*>(g_V + ((size_t)((b0i * NHh + h) * Sn + s0)) * HDd + hd) = make_float2(v00, v01);
                *reinterpret_cast<float2*>(g_V + ((size_t)((b1i * NHh + h) * Sn + s1)) * HDd + hd) = make_float2(v10, v11);
            } else {
                const int h0  = col0 >> 6;
                const int hd0 = col0 & 63;
                const int h1  = (col0 + 1) >> 6;
                const int hd1 = (col0 + 1) & 63;
                const int b0i = r0 >> 11, s0 = r0 & (Sn - 1);
                const int b1i = r1 >> 11, s1 = r1 & (Sn - 1);
                C[((size_t)((b0i * NHh + h0) * HDd + hd0)) * Sn + s0] = v00;
                C[((size_t)((b0i * NHh + h1) * HDd + hd1)) * Sn + s0] = v01;
                C[((size_t)((b1i * NHh + h0) * HDd + hd0)) * Sn + s1] = v10;
                C[((size_t)((b1i * NHh + h1) * HDd + hd1)) * Sn + s1] = v11;
            }
        }
    }
}

// ---------------------------------------------------------------------------
// Flash attention (unchanged, proven): per (b, h, q-tile of 128). Tk = 64.
// Qt/Kt: [bh][hd][s] (Q pre-scaled); V: [bh][s][hd]. Output Y: [B,S,D].
// ---------------------------------------------------------------------------
#define TQ 128
#define TK 64
#define PSTR 132

__global__ __launch_bounds__(256, 2)
void attn_kernel(const float* __restrict__ Qt, const float* __restrict__ Kt,
                 const float* __restrict__ V, float* __restrict__ Y)
{
    extern __shared__ float smf[];
    float* Qs = smf;
    float* Ks = Qs + HDd * TQ;
    float* Vs = Ks + HDd * TK;
    float* Ps = Vs + TK * HDd;

    const int tid = threadIdx.x;
    const int tx  = tid & 15;
    const int ty  = tid >> 4;
    const int q0  = blockIdx.x * TQ;
    const int h   = blockIdx.y;
    const int b   = blockIdx.z;
    const int bh  = b * NHh + h;

    {
        const float* Qb = Qt + (size_t)bh * HDd * Sn + q0;
        for (int f = tid; f < HDd * TQ / 4; f += 256) {
            const int row = f >> 5;
            const int c4  = f & 31;
            *reinterpret_cast<float4*>(Qs + row * TQ + c4 * 4) =
                *reinterpret_cast<const float4*>(Qb + (size_t)row * Sn + c4 * 4);
        }
    }

    float m_[8], l_[8], o_[8][4];
#pragma unroll
    for (int i = 0; i < 8; ++i) {
        m_[i] = -1e30f;
        l_[i] = 0.0f;
#pragma unroll
        for (int j = 0; j < 4; ++j) o_[i][j] = 0.0f;
    }

    const float* Kb = Kt + (size_t)bh * HDd * Sn;
    const float* Vb = V  + (size_t)bh * Sn * HDd;

    for (int k0 = 0; k0 < Sn; k0 += TK) {
        __syncthreads();

        for (int f = tid; f < HDd * TK / 4; f += 256) {
            const int row = f >> 4;
            const int c4  = f & 15;
            *reinterpret_cast<float4*>(Ks + row * TK + c4 * 4) =
                *reinterpret_cast<const float4*>(Kb + (size_t)row * Sn + k0 + c4 * 4);
        }
        for (int f = tid; f < TK * HDd / 4; f += 256) {
            const int row = f >> 4;
            const int c4  = f & 15;
            *reinterpret_cast<float4*>(Vs + row * HDd + c4 * 4) =
                *reinterpret_cast<const float4*>(Vb + (size_t)(k0 + row) * HDd + c4 * 4);
        }
        __syncthreads();

        float s[8][4];
#pragma unroll
        for (int i = 0; i < 8; ++i)
#pragma unroll
            for (int j = 0; j < 4; ++j) s[i][j] = 0.0f;

#pragma unroll
        for (int kk = 0; kk < HDd; ++kk) {
            float av[8], bv[4];
            *reinterpret_cast<float4*>(&av[0]) = *reinterpret_cast<const float4*>(Qs + kk * TQ + ty * 8);
            *reinterpret_cast<float4*>(&av[4]) = *reinterpret_cast<const float4*>(Qs + kk * TQ + ty * 8 + 4);
            *reinterpret_cast<float4*>(&bv[0]) = *reinterpret_cast<const float4*>(Ks + kk * TK + tx * 4);
#pragma unroll
            for (int i = 0; i < 8; ++i)
#pragma unroll
                for (int j = 0; j < 4; ++j)
                    s[i][j] += av[i] * bv[j];
        }

#pragma unroll
        for (int i = 0; i < 8; ++i) {
            float rmax = fmaxf(fmaxf(s[i][0], s[i][1]), fmaxf(s[i][2], s[i][3]));
#pragma unroll
            for (int off = 1; off < 16; off <<= 1)
                rmax = fmaxf(rmax, __shfl_xor_sync(0xffffffffu, rmax, off, 16));
            const float mnew  = fmaxf(m_[i], rmax);
            const float alpha = __expf(m_[i] - mnew);
            float rsum = 0.0f;
#pragma unroll
            for (int j = 0; j < 4; ++j) {
                const float p = __expf(s[i][j] - mnew);
                s[i][j] = p;
                rsum += p;
            }
#pragma unroll
            for (int off = 1; off < 16; off <<= 1)
                rsum += __shfl_xor_sync(0xffffffffu, rsum, off, 16);
            l_[i] = l_[i] * alpha + rsum;
            m_[i] = mnew;
#pragma unroll
            for (int j = 0; j < 4; ++j) o_[i][j] *= alpha;
        }

#pragma unroll
        for (int j = 0; j < 4; ++j) {
            float4 v0 = make_float4(s[0][j], s[1][j], s[2][j], s[3][j]);
            float4 v1 = make_float4(s[4][j], s[5][j], s[6][j], s[7][j]);
            float* dst = Ps + (tx * 4 + j) * PSTR + ty * 8;
            *reinterpret_cast<float4*>(dst)     = v0;
            *reinterpret_cast<float4*>(dst + 4) = v1;
        }
        __syncthreads();

#pragma unroll
        for (int kk = 0; kk < TK; ++kk) {
            float av[8], bv[4];
            *reinterpret_cast<float4*>(&av[0]) = *reinterpret_cast<const float4*>(Ps + kk * PSTR + ty * 8);
            *reinterpret_cast<float4*>(&av[4]) = *reinterpret_cast<const float4*>(Ps + kk * PSTR + ty * 8 + 4);
            *reinterpret_cast<float4*>(&bv[0]) = *reinterpret_cast<const float4*>(Vs + kk * HDd + tx * 4);
#pragma unroll
            for (int i = 0; i < 8; ++i)
#pragma unroll
                for (int j = 0; j < 4; ++j)
                    o_[i][j] += av[i] * bv[j];
        }
    }

#pragma unroll
    for (int i = 0; i < 8; ++i) {
        const float inv = 1.0f / l_[i];
        const int q = q0 + ty * 8 + i;
        float4 v = make_float4(o_[i][0] * inv, o_[i][1] * inv,
                               o_[i][2] * inv, o_[i][3] * inv);
        *reinterpret_cast<float4*>(Y + ((size_t)(b * Sn + q)) * Dn + h * HDd + tx * 4) = v;
    }
}

// ---------------------------------------------------------------------------
extern "C" void kernel_launch(void* const* d_in, const int* in_sizes, int n_in,
                              void* d_out, int out_size)
{
    const float* x  = (const float*)d_in[0];
    const float* Wq = (const float*)d_in[1];
    const float* Wk = (const float*)d_in[2];
    const float* Wv = (const float*)d_in[3];
    const float* Wo = (const float*)d_in[4];
    float* out = (float*)d_out;

    float *qt, *kt, *v, *y;
    cudaGetSymbolAddress((void**)&qt, g_Qt);
    cudaGetSymbolAddress((void**)&kt, g_Kt);
    cudaGetSymbolAddress((void**)&v,  g_V);
    cudaGetSymbolAddress((void**)&y,  g_Y);

    constexpr int ATTN_SMEM = (HDd * TQ + HDd * TK + TK * HDd + TK * PSTR) * (int)sizeof(float);
    cudaFuncSetAttribute(attn_kernel, cudaFuncAttributeMaxDynamicSharedMemorySize, ATTN_SMEM);

    const dim3 gg(MTOT / 128, Dn / 128);

    // Projections on tf32 mma.sync (scale 1/sqrt(64) folded into Q)
    gemm_mma<<<gg, 256>>>(x, Wq, qt, 0, 0.125f);
    gemm_mma<<<gg, 256>>>(x, Wk, kt, 0, 1.0f);
    gemm_mma<<<gg, 256>>>(x, Wv, v,  1, 1.0f);

    // Flash attention (fp32 SIMT, unchanged)
    attn_kernel<<<dim3(Sn / TQ, NHh, Bn), 256, ATTN_SMEM>>>(qt, kt, v, y);

    // Output projection on tf32 mma.sync
    gemm_mma<<<gg, 256>>>(y, Wo, out, 2, 1.0f);
}

// round 6
// speedup vs baseline: 2.6914x; 1.9760x over previous
#include <cuda_runtime.h>
#include <cstdint>

// Problem constants
#define Bn  4
#define Sn  2048
#define Dn  1024
#define NHh 16
#define HDd 64
#define MTOT (Bn * Sn)   // 8192

// Scratch (static __device__ — no allocations allowed)
__device__ float g_Q [Bn * NHh * Sn * HDd];   // [bh][s][hd]  (pre-scaled by 1/8)
__device__ float g_K [Bn * NHh * Sn * HDd];   // [bh][s][hd]
__device__ float g_Vt[Bn * NHh * HDd * Sn];   // [bh][hd][s]  (transposed)
__device__ float g_Y [Bn * Sn * Dn];          // [b][s][d] attention output

// ---------------------------------------------------------------------------
// mma helpers (base PTX ISA — compute_100-safe)
// ---------------------------------------------------------------------------
__device__ __forceinline__ uint32_t f2tf32(float f) {
    uint32_t r;
    asm("cvt.rna.tf32.f32 %0, %1;" : "=r"(r) : "f"(f));
    return r;
}

__device__ __forceinline__ void mma_tf32(float c[4],
                                         uint32_t a0, uint32_t a1, uint32_t a2, uint32_t a3,
                                         uint32_t b0, uint32_t b1) {
    asm volatile(
        "mma.sync.aligned.m16n8k8.row.col.f32.tf32.tf32.f32 "
        "{%0,%1,%2,%3}, {%4,%5,%6,%7}, {%8,%9}, {%0,%1,%2,%3};"
        : "+f"(c[0]), "+f"(c[1]), "+f"(c[2]), "+f"(c[3])
        : "r"(a0), "r"(a1), "r"(a2), "r"(a3), "r"(b0), "r"(b1));
}

// pack two fp32 into f16x2: lo -> low half, hi -> high half
__device__ __forceinline__ uint32_t packh2(float lo, float hi) {
    uint32_t r;
    asm("cvt.rn.f16x2.f32 %0, %1, %2;" : "=r"(r) : "f"(hi), "f"(lo));
    return r;
}

__device__ __forceinline__ void mma_f16(float c[4],
                                        uint32_t a0, uint32_t a1, uint32_t a2, uint32_t a3,
                                        uint32_t b0, uint32_t b1) {
    asm volatile(
        "mma.sync.aligned.m16n8k16.row.col.f32.f16.f16.f32 "
        "{%0,%1,%2,%3}, {%4,%5,%6,%7}, {%8,%9}, {%0,%1,%2,%3};"
        : "+f"(c[0]), "+f"(c[1]), "+f"(c[2]), "+f"(c[3])
        : "r"(a0), "r"(a1), "r"(a2), "r"(a3), "r"(b0), "r"(b1));
}

// ===========================================================================
// Tensor-core GEMM (tf32, proven): C = A @ W^T.
// mode 0: head-transposed:  C[((b*NH+h)*HD+hd)*S + s]
// mode 1: head-natural:     C[((b*NH+h)*S+s)*HD + hd]
// mode 2: plain row-major:  C[m*1024 + n]
// ===========================================================================
#define GSTR 20

__global__ __launch_bounds__(256, 1)
void gemm_mma(const float* __restrict__ A, const float* __restrict__ W,
              float* __restrict__ C, int mode, float scale)
{
    constexpr int BM = 128, BK = 16;
    __shared__ uint32_t As[2][BM * GSTR];
    __shared__ uint32_t Bs[2][BM * GSTR];

    const int tid  = threadIdx.x;
    const int wid  = tid >> 5;
    const int lane = tid & 31;
    const int wm   = wid >> 2;
    const int wn   = wid & 3;
    const int mw   = wm * 64;
    const int nw   = wn * 32;
    const int g    = lane >> 2;
    const int t    = lane & 3;
    const int m0   = blockIdx.x * 128;
    const int n0   = blockIdx.y * 128;

    const int lr = tid >> 1;
    const int lc = (tid & 1) * 8;
    const float* Ap = A + (size_t)(m0 + lr) * Dn + lc;
    const float* Wp = W + (size_t)(n0 + lr) * Dn + lc;

    float4 pa0, pa1, pb0, pb1;

    float c[4][4][4];
#pragma unroll
    for (int i = 0; i < 4; ++i)
#pragma unroll
        for (int j = 0; j < 4; ++j)
#pragma unroll
            for (int e = 0; e < 4; ++e) c[i][j][e] = 0.0f;

    {
        pa0 = *reinterpret_cast<const float4*>(Ap);
        pa1 = *reinterpret_cast<const float4*>(Ap + 4);
        pb0 = *reinterpret_cast<const float4*>(Wp);
        pb1 = *reinterpret_cast<const float4*>(Wp + 4);
        uint32_t* da = &As[0][lr * GSTR + lc];
        da[0] = f2tf32(pa0.x); da[1] = f2tf32(pa0.y);
        da[2] = f2tf32(pa0.z); da[3] = f2tf32(pa0.w);
        da[4] = f2tf32(pa1.x); da[5] = f2tf32(pa1.y);
        da[6] = f2tf32(pa1.z); da[7] = f2tf32(pa1.w);
        uint32_t* db = &Bs[0][lr * GSTR + lc];
        db[0] = f2tf32(pb0.x); db[1] = f2tf32(pb0.y);
        db[2] = f2tf32(pb0.z); db[3] = f2tf32(pb0.w);
        db[4] = f2tf32(pb1.x); db[5] = f2tf32(pb1.y);
        db[6] = f2tf32(pb1.z); db[7] = f2tf32(pb1.w);
    }
    __syncthreads();

    constexpr int NT = Dn / BK;
    for (int kt = 0; kt < NT; ++kt) {
        const int cur = kt & 1;
        if (kt + 1 < NT) {
            const float* a = Ap + (kt + 1) * BK;
            pa0 = *reinterpret_cast<const float4*>(a);
            pa1 = *reinterpret_cast<const float4*>(a + 4);
            const float* w = Wp + (kt + 1) * BK;
            pb0 = *reinterpret_cast<const float4*>(w);
            pb1 = *reinterpret_cast<const float4*>(w + 4);
        }

#pragma unroll
        for (int ks = 0; ks < BK; ks += 8) {
            uint32_t a[4][4], b[4][2];
#pragma unroll
            for (int f = 0; f < 4; ++f) {
                const int r = mw + f * 16 + g;
                a[f][0] = As[cur][r * GSTR + ks + t];
                a[f][1] = As[cur][(r + 8) * GSTR + ks + t];
                a[f][2] = As[cur][r * GSTR + ks + t + 4];
                a[f][3] = As[cur][(r + 8) * GSTR + ks + t + 4];
            }
#pragma unroll
            for (int f = 0; f < 4; ++f) {
                const int n = nw + f * 8 + g;
                b[f][0] = Bs[cur][n * GSTR + ks + t];
                b[f][1] = Bs[cur][n * GSTR + ks + t + 4];
            }
#pragma unroll
            for (int i = 0; i < 4; ++i)
#pragma unroll
                for (int j = 0; j < 4; ++j)
                    mma_tf32(c[i][j], a[i][0], a[i][1], a[i][2], a[i][3],
                             b[j][0], b[j][1]);
        }

        if (kt + 1 < NT) {
            const int nxt = (kt + 1) & 1;
            uint32_t* da = &As[nxt][lr * GSTR + lc];
            da[0] = f2tf32(pa0.x); da[1] = f2tf32(pa0.y);
            da[2] = f2tf32(pa0.z); da[3] = f2tf32(pa0.w);
            da[4] = f2tf32(pa1.x); da[5] = f2tf32(pa1.y);
            da[6] = f2tf32(pa1.z); da[7] = f2tf32(pa1.w);
            uint32_t* db = &Bs[nxt][lr * GSTR + lc];
            db[0] = f2tf32(pb0.x); db[1] = f2tf32(pb0.y);
            db[2] = f2tf32(pb0.z); db[3] = f2tf32(pb0.w);
            db[4] = f2tf32(pb1.x); db[5] = f2tf32(pb1.y);
            db[6] = f2tf32(pb1.z); db[7] = f2tf32(pb1.w);
        }
        __syncthreads();
    }

#pragma unroll
    for (int i = 0; i < 4; ++i) {
        const int r0 = m0 + mw + i * 16 + g;
        const int r1 = r0 + 8;
#pragma unroll
        for (int j = 0; j < 4; ++j) {
            const int col0 = n0 + nw + j * 8 + 2 * t;
            const float v00 = c[i][j][0] * scale;
            const float v01 = c[i][j][1] * scale;
            const float v10 = c[i][j][2] * scale;
            const float v11 = c[i][j][3] * scale;
            if (mode == 2) {
                *reinterpret_cast<float2*>(C + (size_t)r0 * Dn + col0) = make_float2(v00, v01);
                *reinterpret_cast<float2*>(C + (size_t)r1 * Dn + col0) = make_float2(v10, v11);
            } else if (mode == 1) {
                const int h   = col0 >> 6;
                const int hd  = col0 & 63;
                const int b0i = r0 >> 11, s0 = r0 & (Sn - 1);
                const int b1i = r1 >> 11, s1 = r1 & (Sn - 1);
                *reinterpret_cast<float2*>(C + ((size_t)((b0i * NHh + h) * Sn + s0)) * HDd + hd) = make_float2(v00, v01);
                *reinterpret_cast<float2*>(C + ((size_t)((b1i * NHh + h) * Sn + s1)) * HDd + hd) = make_float2(v10, v11);
            } else {
                const int h0  = col0 >> 6;
                const int hd0 = col0 & 63;
                const int h1  = (col0 + 1) >> 6;
                const int hd1 = (col0 + 1) & 63;
                const int b0i = r0 >> 11, s0 = r0 & (Sn - 1);
                const int b1i = r1 >> 11, s1 = r1 & (Sn - 1);
                C[((size_t)((b0i * NHh + h0) * HDd + hd0)) * Sn + s0] = v00;
                C[((size_t)((b0i * NHh + h1) * HDd + hd1)) * Sn + s0] = v01;
                C[((size_t)((b1i * NHh + h0) * HDd + hd0)) * Sn + s1] = v10;
                C[((size_t)((b1i * NHh + h1) * HDd + hd1)) * Sn + s1] = v11;
            }
        }
    }
}

// ===========================================================================
// Flash attention on fp16 mma.sync (m16n8k16), fp32 softmax/accum.
// Q,K: [bh][s][hd] fp32 (Q pre-scaled by 1/8); Vt: [bh][hd][s] fp32.
// CTA: 128 q-rows, 8 warps x 16 rows; key tile 64; 32 tiles.
// Smem: K tile [64 key][64 hd] f16, Vt tile [64 hd][64 key] f16, both stored
// pair-interleaved within 16-col groups (word order 0,4,1,5,2,6,3,7 of pairs)
// so B-fragments (b0,b1) are a single LDS.64; row stride 36 words (pad 4).
// ===========================================================================
__global__ __launch_bounds__(256, 2)
void attn_f16(const float* __restrict__ Q, const float* __restrict__ K,
              const float* __restrict__ Vt, float* __restrict__ Y)
{
    __shared__ uint32_t sK[64 * 36];
    __shared__ uint32_t sV[64 * 36];

    const int tid  = threadIdx.x;
    const int wid  = tid >> 5;
    const int lane = tid & 31;
    const int g    = lane >> 2;
    const int t    = lane & 3;
    const int q0   = blockIdx.x * 128;
    const int h    = blockIdx.y;
    const int b    = blockIdx.z;
    const int bh   = b * NHh + h;

    const float* Qb = Q  + (size_t)bh * Sn * HDd;
    const float* Kb = K  + (size_t)bh * Sn * HDd;
    const float* Vb = Vt + (size_t)bh * HDd * Sn;

    // Q fragments: rows r0 = q0 + wid*16 + g, r1 = r0 + 8; k-dim = hd (4 k16 steps)
    const int r0 = q0 + wid * 16 + g;
    uint32_t qa[4][4];
#pragma unroll
    for (int ks = 0; ks < 4; ++ks) {
        const float* p0 = Qb + (size_t)r0 * HDd + ks * 16 + 2 * t;
        const float* p1 = p0 + 8 * HDd;
        float2 x0 = *reinterpret_cast<const float2*>(p0);
        float2 x1 = *reinterpret_cast<const float2*>(p1);
        float2 x2 = *reinterpret_cast<const float2*>(p0 + 8);
        float2 x3 = *reinterpret_cast<const float2*>(p1 + 8);
        qa[ks][0] = packh2(x0.x, x0.y);
        qa[ks][1] = packh2(x1.x, x1.y);
        qa[ks][2] = packh2(x2.x, x2.y);
        qa[ks][3] = packh2(x3.x, x3.y);
    }

    float m_[2] = {-1e30f, -1e30f};
    float l_[2] = {0.0f, 0.0f};
    float o[8][4];
#pragma unroll
    for (int nf = 0; nf < 8; ++nf)
#pragma unroll
        for (int e = 0; e < 4; ++e) o[nf][e] = 0.0f;

    for (int k0 = 0; k0 < Sn; k0 += 64) {
        __syncthreads();
        // ------- fill K (key-major) and V^T (hd-major) tiles, f16 interleaved
#pragma unroll
        for (int f = 0; f < 4; ++f) {
            const int idx = tid + f * 256;     // 0..1023
            const int row = idx >> 4;          // 0..63
            const int c4  = idx & 15;          // float4 index
            const int grp = c4 >> 2;
            const int p0  = (c4 & 3) * 2;
            const int pos0 = (p0 & 3) * 2 + (p0 >> 2);
            const int pos1 = ((p0 + 1) & 3) * 2 + ((p0 + 1) >> 2);
            const int base = row * 36 + grp * 8;
            float4 kv = *reinterpret_cast<const float4*>(
                Kb + (size_t)(k0 + row) * HDd + c4 * 4);
            sK[base + pos0] = packh2(kv.x, kv.y);
            sK[base + pos1] = packh2(kv.z, kv.w);
            float4 vv = *reinterpret_cast<const float4*>(
                Vb + (size_t)row * Sn + k0 + c4 * 4);
            sV[base + pos0] = packh2(vv.x, vv.y);
            sV[base + pos1] = packh2(vv.z, vv.w);
        }
        __syncthreads();

        // ------- scores: S = Q K^T  (8 n-frags of keys, 4 hd k-steps)
        float sc[8][4];
#pragma unroll
        for (int j = 0; j < 8; ++j)
#pragma unroll
            for (int e = 0; e < 4; ++e) sc[j][e] = 0.0f;

#pragma unroll
        for (int j = 0; j < 8; ++j) {
#pragma unroll
            for (int ks = 0; ks < 4; ++ks) {
                uint2 bb = *reinterpret_cast<const uint2*>(
                    sK + (8 * j + g) * 36 + ks * 8 + 2 * t);
                mma_f16(sc[j], qa[ks][0], qa[ks][1], qa[ks][2], qa[ks][3],
                        bb.x, bb.y);
            }
        }

        // ------- online softmax (rows g and g+8; quad lanes share a row)
        float mx0 = m_[0], mx1 = m_[1];
#pragma unroll
        for (int j = 0; j < 8; ++j) {
            mx0 = fmaxf(mx0, fmaxf(sc[j][0], sc[j][1]));
            mx1 = fmaxf(mx1, fmaxf(sc[j][2], sc[j][3]));
        }
        mx0 = fmaxf(mx0, __shfl_xor_sync(0xffffffffu, mx0, 1));
        mx0 = fmaxf(mx0, __shfl_xor_sync(0xffffffffu, mx0, 2));
        mx1 = fmaxf(mx1, __shfl_xor_sync(0xffffffffu, mx1, 1));
        mx1 = fmaxf(mx1, __shfl_xor_sync(0xffffffffu, mx1, 2));

        const float alpha0 = __expf(m_[0] - mx0);
        const float alpha1 = __expf(m_[1] - mx1);
        m_[0] = mx0; m_[1] = mx1;

        float rs0 = 0.0f, rs1 = 0.0f;
#pragma unroll
        for (int j = 0; j < 8; ++j) {
            sc[j][0] = __expf(sc[j][0] - mx0); rs0 += sc[j][0];
            sc[j][1] = __expf(sc[j][1] - mx0); rs0 += sc[j][1];
            sc[j][2] = __expf(sc[j][2] - mx1); rs1 += sc[j][2];
            sc[j][3] = __expf(sc[j][3] - mx1); rs1 += sc[j][3];
        }
        rs0 += __shfl_xor_sync(0xffffffffu, rs0, 1);
        rs0 += __shfl_xor_sync(0xffffffffu, rs0, 2);
        rs1 += __shfl_xor_sync(0xffffffffu, rs1, 1);
        rs1 += __shfl_xor_sync(0xffffffffu, rs1, 2);
        l_[0] = l_[0] * alpha0 + rs0;
        l_[1] = l_[1] * alpha1 + rs1;

#pragma unroll
        for (int nf = 0; nf < 8; ++nf) {
            o[nf][0] *= alpha0; o[nf][1] *= alpha0;
            o[nf][2] *= alpha1; o[nf][3] *= alpha1;
        }

        // ------- O += P V  (P packs directly from score frags; k-dim = keys)
#pragma unroll
        for (int ks = 0; ks < 4; ++ks) {
            const uint32_t pa0 = packh2(sc[2 * ks][0],     sc[2 * ks][1]);
            const uint32_t pa1 = packh2(sc[2 * ks][2],     sc[2 * ks][3]);
            const uint32_t pa2 = packh2(sc[2 * ks + 1][0], sc[2 * ks + 1][1]);
            const uint32_t pa3 = packh2(sc[2 * ks + 1][2], sc[2 * ks + 1][3]);
#pragma unroll
            for (int nf = 0; nf < 8; ++nf) {
                uint2 bb = *reinterpret_cast<const uint2*>(
                    sV + (8 * nf + g) * 36 + ks * 8 + 2 * t);
                mma_f16(o[nf], pa0, pa1, pa2, pa3, bb.x, bb.y);
            }
        }
    }

    // ------- epilogue: normalize, write Y [B,S,D]
    const float inv0 = 1.0f / l_[0];
    const float inv1 = 1.0f / l_[1];
    float* Y0 = Y + ((size_t)(b * Sn + r0)) * Dn + h * HDd;
    float* Y1 = Y0 + (size_t)8 * Dn;
#pragma unroll
    for (int nf = 0; nf < 8; ++nf) {
        const int col = 8 * nf + 2 * t;
        *reinterpret_cast<float2*>(Y0 + col) = make_float2(o[nf][0] * inv0, o[nf][1] * inv0);
        *reinterpret_cast<float2*>(Y1 + col) = make_float2(o[nf][2] * inv1, o[nf][3] * inv1);
    }
}

// ---------------------------------------------------------------------------
extern "C" void kernel_launch(void* const* d_in, const int* in_sizes, int n_in,
                              void* d_out, int out_size)
{
    const float* x  = (const float*)d_in[0];
    const float* Wq = (const float*)d_in[1];
    const float* Wk = (const float*)d_in[2];
    const float* Wv = (const float*)d_in[3];
    const float* Wo = (const float*)d_in[4];
    float* out = (float*)d_out;

    float *q, *k, *vt, *y;
    cudaGetSymbolAddress((void**)&q,  g_Q);
    cudaGetSymbolAddress((void**)&k,  g_K);
    cudaGetSymbolAddress((void**)&vt, g_Vt);
    cudaGetSymbolAddress((void**)&y,  g_Y);

    const dim3 gg(MTOT / 128, Dn / 128);

    // Projections on tf32 mma.sync (softmax scale folded into Q)
    gemm_mma<<<gg, 256>>>(x, Wq, q,  1, 0.125f);
    gemm_mma<<<gg, 256>>>(x, Wk, k,  1, 1.0f);
    gemm_mma<<<gg, 256>>>(x, Wv, vt, 0, 1.0f);

    // Flash attention on fp16 mma.sync
    attn_f16<<<dim3(Sn / 128, NHh, Bn), 256>>>(q, k, vt, y);

    // Output projection
    gemm_mma<<<gg, 256>>>(y, Wo, out, 2, 1.0f);
}